// round 7
// baseline (speedup 1.0000x reference)
#include <cuda_runtime.h>
#include <cuda_bf16.h>
#include <cstdint>

// out[n][s] = dot(x[n,:], weight[ids[s],:]) + bias[ids[s]]
//   x [256,512] f32, weight [500001,512] f32, bias [500001] f32, ids [32768] i32
//   out [256, 32768] f32
// bf16x3 split GEMM on mma.sync. Round 7: warp tile 32x64 (16 MAC/smem-byte),
// CTA tile 64 samples x 256 x-rows, KC=32 with hi/lo packed per 128B row,
// 2 CTAs/SM (80KB smem, <=128 regs).

namespace {
constexpr int D_K    = 512;
constexpr int NX     = 256;
constexpr int S_ALL  = 32768;
constexpr int ROWS_W = 500001;
constexpr int STILE  = 64;         // samples per CTA (GEMM M)
constexpr int KC     = 32;         // f32 K elems per chunk
constexpr int NCH    = D_K / KC;   // 16
constexpr int THREADS = 256;

// stage layout (bytes). Each row = 128B: [32 bf16 hi | 32 bf16 lo], sw128.
constexpr uint32_t A_OFF = 0;          // 64 rows  x 128B = 8KB
constexpr uint32_t B_OFF = 8192;       // 256 rows x 128B = 32KB
constexpr uint32_t STAGE = 40960;      // 40KB
constexpr uint32_t SMEM_BYTES = 2 * STAGE;   // 80KB (epilogue reuses this)
constexpr int CSTRIDE = 260;           // f32 stride of epilogue staging (64 x 260)
}

__device__ __nv_bfloat16 g_xh[NX * D_K];
__device__ __nv_bfloat16 g_xl[NX * D_K];

__device__ __forceinline__ uint32_t smem_u32(const void* p) {
    uint32_t a;
    asm("{ .reg .u64 t; cvta.to.shared.u64 t, %1; cvt.u32.u64 %0, t; }" : "=r"(a) : "l"(p));
    return a;
}
__device__ __forceinline__ uint32_t sw128(uint32_t o) { return o ^ ((o >> 3) & 0x70u); }

__device__ __forceinline__ uint32_t pk(__nv_bfloat16 a, __nv_bfloat16 b) {
    __nv_bfloat162 t = __halves2bfloat162(a, b);
    return *reinterpret_cast<uint32_t*>(&t);
}
__device__ __forceinline__ uint32_t pkf(float a, float b) {
    __nv_bfloat162 t = __floats2bfloat162_rn(a, b);
    return *reinterpret_cast<uint32_t*>(&t);
}

__device__ __forceinline__ void ldsm4(uint32_t addr, uint32_t& r0, uint32_t& r1,
                                      uint32_t& r2, uint32_t& r3) {
    asm volatile("ldmatrix.sync.aligned.m8n8.x4.shared.b16 {%0,%1,%2,%3}, [%4];"
                 : "=r"(r0), "=r"(r1), "=r"(r2), "=r"(r3) : "r"(addr));
}
__device__ __forceinline__ void mma16816(float* d, const uint32_t* a, const uint32_t* b) {
    asm volatile(
        "mma.sync.aligned.m16n8k16.row.col.f32.bf16.bf16.f32 "
        "{%0,%1,%2,%3}, {%4,%5,%6,%7}, {%8,%9}, {%0,%1,%2,%3};"
        : "+f"(d[0]), "+f"(d[1]), "+f"(d[2]), "+f"(d[3])
        : "r"(a[0]), "r"(a[1]), "r"(a[2]), "r"(a[3]), "r"(b[0]), "r"(b[1]));
}
__device__ __forceinline__ void cp16(uint32_t dst, const void* src) {
    asm volatile("cp.async.ca.shared.global [%0], [%1], 16;" :: "r"(dst), "l"(src));
}

// ---------- kernel 1: split x into bf16 hi/lo ----------
__global__ void split_x_kernel(const float* __restrict__ x) {
    int i = blockIdx.x * blockDim.x + threadIdx.x;   // over 32768 float4s
    float4 v = reinterpret_cast<const float4*>(x)[i];
    __nv_bfloat16 h0 = __float2bfloat16_rn(v.x), h1 = __float2bfloat16_rn(v.y);
    __nv_bfloat16 h2 = __float2bfloat16_rn(v.z), h3 = __float2bfloat16_rn(v.w);
    uint2 hv, lv;
    hv.x = pk(h0, h1);  hv.y = pk(h2, h3);
    lv.x = pkf(v.x - __bfloat162float(h0), v.y - __bfloat162float(h1));
    lv.y = pkf(v.z - __bfloat162float(h2), v.w - __bfloat162float(h3));
    reinterpret_cast<uint2*>(g_xh)[i] = hv;
    reinterpret_cast<uint2*>(g_xl)[i] = lv;
}

// ---------- kernel 2: GEMM ----------
__global__ void __launch_bounds__(THREADS, 2)
lsh_mma_gemm(const float* __restrict__ weight,
             const float* __restrict__ bias,
             const int* __restrict__ sample_ids,
             float* __restrict__ out)
{
    extern __shared__ float4 smem4[];
    char* smc = reinterpret_cast<char*>(smem4);
    const uint32_t sb = smem_u32(smc);

    __shared__ int   sids[STILE];
    __shared__ float sbias[STILE];

    const int tid = threadIdx.x;
    const int wid = tid >> 5;
    const int lid = tid & 31;
    const int s0  = blockIdx.x * STILE;    // sample tile

    if (tid < STILE) {
        int id = sample_ids[s0 + tid];
        id = min(max(id, 0), ROWS_W - 1);
        sids[tid]  = id;
        sbias[tid] = bias[id];
    }
    __syncthreads();

    // ---- A loader coords: 64 gathered weight rows, 4 threads/row ----
    const int arow = tid >> 2;               // 0..63
    const int aq   = (tid & 3) * 8;          // 8-float segment within 32-float slice

    // ---- warp / mma coords: 2(M) x 4(N) warp grid, warp tile 32x64 ----
    const int warp_m = wid & 1;
    const int warp_n = wid >> 1;
    const uint32_t a_lrow  = (uint32_t)(warp_m * 32 + (lid & 15));
    const uint32_t a_lsub  = (uint32_t)(lid >> 4) * 16u;
    const uint32_t b_lrow0 = (uint32_t)(warp_n * 64 + ((lid >> 4) & 1) * 8 + (lid & 7));
    const uint32_t b_lko   = (uint32_t)((lid >> 3) & 1) * 16u;

    float d[2][8][4];
    #pragma unroll
    for (int mt = 0; mt < 2; mt++)
        #pragma unroll
        for (int nf = 0; nf < 8; nf++)
            #pragma unroll
            for (int r = 0; r < 4; r++) d[mt][nf][r] = 0.f;

    float4 av[2];

    auto loadA = [&](int c) {
        const float* wrow = weight + (size_t)sids[arow] * D_K + c * KC + aq;
        av[0] = reinterpret_cast<const float4*>(wrow)[0];
        av[1] = reinterpret_cast<const float4*>(wrow)[1];
    };
    auto cpB = [&](int c, uint32_t stg) {
        #pragma unroll
        for (int p = 0; p < 4; p++) {
            int idx = tid + p * THREADS;     // 1024: 256 rows x 4 segs
            int row = idx >> 2, sg = idx & 3;
            size_t gi = (size_t)row * D_K + c * KC + sg * 8;
            uint32_t dh = sw128((uint32_t)row * 128u + (uint32_t)sg * 16u);
            uint32_t dl = sw128((uint32_t)row * 128u + 64u + (uint32_t)sg * 16u);
            cp16(sb + stg + B_OFF + dh, g_xh + gi);
            cp16(sb + stg + B_OFF + dl, g_xl + gi);
        }
    };
    auto storeA = [&](uint32_t stg) {
        #pragma unroll
        for (int j = 0; j < 2; j++) {
            float4 v = av[j];
            __nv_bfloat16 h0 = __float2bfloat16_rn(v.x), h1 = __float2bfloat16_rn(v.y);
            __nv_bfloat16 h2 = __float2bfloat16_rn(v.z), h3 = __float2bfloat16_rn(v.w);
            uint2 hv, lv;
            hv.x = pk(h0, h1); hv.y = pk(h2, h3);
            lv.x = pkf(v.x - __bfloat162float(h0), v.y - __bfloat162float(h1));
            lv.y = pkf(v.z - __bfloat162float(h2), v.w - __bfloat162float(h3));
            uint32_t col2 = (uint32_t)(aq + j * 4) * 2u;   // byte offset in 64B half
            *reinterpret_cast<uint2*>(smc + stg + A_OFF +
                sw128((uint32_t)arow * 128u + col2)) = hv;
            *reinterpret_cast<uint2*>(smc + stg + A_OFF +
                sw128((uint32_t)arow * 128u + 64u + col2)) = lv;
        }
    };

    // ---------- prologue: chunk 0 ----------
    loadA(0);
    cpB(0, 0);
    storeA(0);
    asm volatile("cp.async.wait_all;" ::: "memory");
    __syncthreads();

    // ---------- main loop ----------
    for (int c = 0; c < NCH; c++) {
        const uint32_t cur = (uint32_t)(c & 1) * STAGE;
        const uint32_t nxt = (uint32_t)((c + 1) & 1) * STAGE;

        if (c + 1 < NCH) {
            loadA(c + 1);
            cpB(c + 1, nxt);
        }

        // ---- compute chunk c: 2 k-steps of 16 ----
        #pragma unroll
        for (int ks = 0; ks < 2; ks++) {
            uint32_t ah[2][4], al[2][4];
            #pragma unroll
            for (int mt = 0; mt < 2; mt++) {
                uint32_t base = (a_lrow + (uint32_t)mt * 16u) * 128u +
                                (uint32_t)ks * 32u + a_lsub;
                ldsm4(sb + cur + A_OFF + sw128(base),
                      ah[mt][0], ah[mt][1], ah[mt][2], ah[mt][3]);
                ldsm4(sb + cur + A_OFF + sw128(base + 64u),
                      al[mt][0], al[mt][1], al[mt][2], al[mt][3]);
            }
            #pragma unroll
            for (int h = 0; h < 2; h++) {          // two nf-halves: limits B frag regs
                uint32_t bh[4][2], bl[4][2];
                #pragma unroll
                for (int i = 0; i < 2; i++) {
                    int nf2 = h * 2 + i;
                    uint32_t base = (b_lrow0 + (uint32_t)nf2 * 16u) * 128u +
                                    (uint32_t)ks * 32u + b_lko;
                    ldsm4(sb + cur + B_OFF + sw128(base),
                          bh[2*i][0], bh[2*i][1], bh[2*i+1][0], bh[2*i+1][1]);
                    ldsm4(sb + cur + B_OFF + sw128(base + 64u),
                          bl[2*i][0], bl[2*i][1], bl[2*i+1][0], bl[2*i+1][1]);
                }
                #pragma unroll
                for (int mt = 0; mt < 2; mt++)
                    #pragma unroll
                    for (int j = 0; j < 4; j++) {
                        int nf = h * 4 + j;
                        mma16816(d[mt][nf], ah[mt], bh[j]);
                        mma16816(d[mt][nf], ah[mt], bl[j]);
                        mma16816(d[mt][nf], al[mt], bh[j]);
                    }
            }
        }

        if (c + 1 < NCH) storeA(nxt);
        asm volatile("cp.async.wait_all;" ::: "memory");
        __syncthreads();
    }

    // ---------- epilogue: smem transpose [m][n] stride 260, bias, coalesced out
    float* C = reinterpret_cast<float*>(smc);   // 64 x 260 f32 = 66.6KB
    #pragma unroll
    for (int mt = 0; mt < 2; mt++) {
        int m0r = warp_m * 32 + mt * 16 + (lid >> 2);
        float b0v = sbias[m0r];
        float b1v = sbias[m0r + 8];
        #pragma unroll
        for (int nf = 0; nf < 8; nf++) {
            int nc = warp_n * 64 + nf * 8 + (lid & 3) * 2;
            float2 v0 = { d[mt][nf][0] + b0v, d[mt][nf][1] + b0v };
            float2 v1 = { d[mt][nf][2] + b1v, d[mt][nf][3] + b1v };
            *reinterpret_cast<float2*>(&C[(size_t)m0r * CSTRIDE + nc])       = v0;
            *reinterpret_cast<float2*>(&C[(size_t)(m0r + 8) * CSTRIDE + nc]) = v1;
        }
    }
    __syncthreads();

    {
        // 2 iterations x 128 rows. thread: n_loc = tid>>1 (+128*it), q = tid&1.
        // reads C[s][n_loc], s = q*4 + k*8: bank = 16q + n_loc(low4) +.. -> conflict-free
        const int q = tid & 1;
        #pragma unroll
        for (int it = 0; it < 2; it++) {
            int n_loc = (tid >> 1) + it * 128;
            float* orow = out + (size_t)n_loc * S_ALL + s0;
            #pragma unroll
            for (int k = 0; k < 8; k++) {
                int s = q * 4 + k * 8;
                float4 v;
                v.x = C[(size_t)(s + 0) * CSTRIDE + n_loc];
                v.y = C[(size_t)(s + 1) * CSTRIDE + n_loc];
                v.z = C[(size_t)(s + 2) * CSTRIDE + n_loc];
                v.w = C[(size_t)(s + 3) * CSTRIDE + n_loc];
                *reinterpret_cast<float4*>(orow + s) = v;
            }
        }
    }
}

extern "C" void kernel_launch(void* const* d_in, const int* in_sizes, int n_in,
                              void* d_out, int out_size)
{
    const float* x    = (const float*)d_in[0];
    const float* w    = (const float*)d_in[1];
    const float* bias = (const float*)d_in[2];
    const int*   ids  = (const int*)d_in[3];
    float*       out  = (float*)d_out;

    cudaFuncSetAttribute(lsh_mma_gemm, cudaFuncAttributeMaxDynamicSharedMemorySize,
                         SMEM_BYTES);

    split_x_kernel<<<128, 256>>>(x);
    lsh_mma_gemm<<<S_ALL / STILE, THREADS, SMEM_BYTES>>>(w, bias, ids, out);
}

// round 8
// speedup vs baseline: 1.0368x; 1.0368x over previous
#include <cuda_runtime.h>
#include <cuda_bf16.h>
#include <cstdint>

// out[n][s] = dot(x[n,:], weight[ids[s],:]) + bias[ids[s]]
//   x [256,512] f32, weight [500001,512] f32, bias [500001] f32, ids [32768] i32
//   out [256, 32768] f32
// bf16x3 split GEMM on mma.sync. Round 8: Round-6 skeleton (KC=64, 8 chunks,
// 64x128 tile, 2 CTAs/SM) + warp tile 32x64 via 2x2x2 (MxNxK-split) warp grid.

namespace {
constexpr int D_K    = 512;
constexpr int NX     = 256;
constexpr int S_ALL  = 32768;
constexpr int ROWS_W = 500001;
constexpr int STILE  = 64;         // samples per CTA (GEMM M)
constexpr int NTILE  = 128;        // x rows per CTA (GEMM N)
constexpr int KC     = 64;         // f32 K elems per chunk
constexpr int NCH    = D_K / KC;   // 8
constexpr int THREADS = 256;

// smem stage layout (bytes): Ah/Al 64 rows x 128B, Bh/Bl 128 rows x 128B
constexpr uint32_t AH = 0, AL = 8192, BH = 16384, BL = 32768;
constexpr uint32_t STAGE = 49152;            // 48KB
constexpr uint32_t SMEM_BYTES = 2 * STAGE;   // 96KB (epilogue reuses this)
constexpr int CSTRIDE = 132;       // f32 stride of epilogue staging (64 x 132)
constexpr int CELEMS  = 64 * CSTRIDE;        // one C buffer (33.8KB); two fit in 96KB
}

__device__ __nv_bfloat16 g_xh[NX * D_K];
__device__ __nv_bfloat16 g_xl[NX * D_K];

__device__ __forceinline__ uint32_t smem_u32(const void* p) {
    uint32_t a;
    asm("{ .reg .u64 t; cvta.to.shared.u64 t, %1; cvt.u32.u64 %0, t; }" : "=r"(a) : "l"(p));
    return a;
}
__device__ __forceinline__ uint32_t sw128(uint32_t o) { return o ^ ((o >> 3) & 0x70u); }

__device__ __forceinline__ uint32_t pk(__nv_bfloat16 a, __nv_bfloat16 b) {
    __nv_bfloat162 t = __halves2bfloat162(a, b);
    return *reinterpret_cast<uint32_t*>(&t);
}
__device__ __forceinline__ uint32_t pkf(float a, float b) {
    __nv_bfloat162 t = __floats2bfloat162_rn(a, b);
    return *reinterpret_cast<uint32_t*>(&t);
}

__device__ __forceinline__ void ldsm4(uint32_t addr, uint32_t& r0, uint32_t& r1,
                                      uint32_t& r2, uint32_t& r3) {
    asm volatile("ldmatrix.sync.aligned.m8n8.x4.shared.b16 {%0,%1,%2,%3}, [%4];"
                 : "=r"(r0), "=r"(r1), "=r"(r2), "=r"(r3) : "r"(addr));
}
__device__ __forceinline__ void mma16816(float* d, const uint32_t* a, const uint32_t* b) {
    asm volatile(
        "mma.sync.aligned.m16n8k16.row.col.f32.bf16.bf16.f32 "
        "{%0,%1,%2,%3}, {%4,%5,%6,%7}, {%8,%9}, {%0,%1,%2,%3};"
        : "+f"(d[0]), "+f"(d[1]), "+f"(d[2]), "+f"(d[3])
        : "r"(a[0]), "r"(a[1]), "r"(a[2]), "r"(a[3]), "r"(b[0]), "r"(b[1]));
}
__device__ __forceinline__ void cp16(uint32_t dst, const void* src) {
    asm volatile("cp.async.ca.shared.global [%0], [%1], 16;" :: "r"(dst), "l"(src));
}

// ---------- kernel 1: split x into bf16 hi/lo ----------
__global__ void split_x_kernel(const float* __restrict__ x) {
    int i = blockIdx.x * blockDim.x + threadIdx.x;   // over 32768 float4s
    float4 v = reinterpret_cast<const float4*>(x)[i];
    __nv_bfloat16 h0 = __float2bfloat16_rn(v.x), h1 = __float2bfloat16_rn(v.y);
    __nv_bfloat16 h2 = __float2bfloat16_rn(v.z), h3 = __float2bfloat16_rn(v.w);
    uint2 hv, lv;
    hv.x = pk(h0, h1);  hv.y = pk(h2, h3);
    lv.x = pkf(v.x - __bfloat162float(h0), v.y - __bfloat162float(h1));
    lv.y = pkf(v.z - __bfloat162float(h2), v.w - __bfloat162float(h3));
    reinterpret_cast<uint2*>(g_xh)[i] = hv;
    reinterpret_cast<uint2*>(g_xl)[i] = lv;
}

// ---------- kernel 2: GEMM ----------
__global__ void __launch_bounds__(THREADS, 2)
lsh_mma_gemm(const float* __restrict__ weight,
             const float* __restrict__ bias,
             const int* __restrict__ sample_ids,
             float* __restrict__ out)
{
    extern __shared__ float4 smem4[];
    char* smc = reinterpret_cast<char*>(smem4);
    const uint32_t sb = smem_u32(smc);

    __shared__ int   sids[STILE];
    __shared__ float sbias[STILE];

    const int tid = threadIdx.x;
    const int wid = tid >> 5;
    const int lid = tid & 31;
    const int n0  = blockIdx.x * NTILE;    // x-row half (0 or 128)
    const int s0  = blockIdx.y * STILE;    // sample tile

    if (tid < STILE) {
        int id = sample_ids[s0 + tid];
        id = min(max(id, 0), ROWS_W - 1);
        sids[tid]  = id;
        sbias[tid] = bias[id];
    }
    __syncthreads();

    // ---- loader coords: A = 64 gathered weight rows, 4 threads/row ----
    const int arow = tid >> 2;               // 0..63
    const int aq   = (tid & 3) * 16;         // 16-float segment within 64-float row

    // ---- warp / mma coords: 2(M) x 2(N) x 2(K-split), warp tile 32x64 ----
    const int warp_m = wid & 1;
    const int warp_n = (wid >> 1) & 1;
    const int warp_k = wid >> 2;
    const uint32_t a_lrow  = (uint32_t)(warp_m * 32 + (lid & 15));
    const uint32_t a_lsub  = (uint32_t)(lid >> 4) * 16u;
    const uint32_t b_lrow0 = (uint32_t)(warp_n * 64 + ((lid >> 4) & 1) * 8 + (lid & 7));
    const uint32_t b_lko   = (uint32_t)((lid >> 3) & 1) * 16u;

    float d[2][8][4];
    #pragma unroll
    for (int mt = 0; mt < 2; mt++)
        #pragma unroll
        for (int nf = 0; nf < 8; nf++)
            #pragma unroll
            for (int r = 0; r < 4; r++) d[mt][nf][r] = 0.f;

    float4 av[4];

    auto loadA = [&](int c) {
        const float* wrow = weight + (size_t)sids[arow] * D_K + c * KC + aq;
        #pragma unroll
        for (int j = 0; j < 4; j++) av[j] = reinterpret_cast<const float4*>(wrow)[j];
    };
    auto cpB = [&](int c, uint32_t stg) {
        #pragma unroll
        for (int p = 0; p < 4; p++) {
            int idx = tid + p * THREADS;     // 1024 segments: 128 rows x 8 segs
            int row = idx >> 3, sg = idx & 7;
            size_t gi = (size_t)(n0 + row) * D_K + c * KC + sg * 8;
            uint32_t dsto = sw128((uint32_t)row * 128u + (uint32_t)sg * 16u);
            cp16(sb + stg + BH + dsto, g_xh + gi);
            cp16(sb + stg + BL + dsto, g_xl + gi);
        }
    };
    auto storeA = [&](uint32_t stg) {
        #pragma unroll
        for (int j = 0; j < 4; j++) {
            float4 v = av[j];
            __nv_bfloat16 h0 = __float2bfloat16_rn(v.x), h1 = __float2bfloat16_rn(v.y);
            __nv_bfloat16 h2 = __float2bfloat16_rn(v.z), h3 = __float2bfloat16_rn(v.w);
            uint2 hv, lv;
            hv.x = pk(h0, h1); hv.y = pk(h2, h3);
            lv.x = pkf(v.x - __bfloat162float(h0), v.y - __bfloat162float(h1));
            lv.y = pkf(v.z - __bfloat162float(h2), v.w - __bfloat162float(h3));
            uint32_t o = sw128((uint32_t)arow * 128u + (uint32_t)(aq + j * 4) * 2u);
            *reinterpret_cast<uint2*>(smc + stg + AH + o) = hv;
            *reinterpret_cast<uint2*>(smc + stg + AL + o) = lv;
        }
    };

    // ---------- prologue: chunk 0 ----------
    loadA(0);
    cpB(0, 0);
    storeA(0);
    asm volatile("cp.async.wait_all;" ::: "memory");
    __syncthreads();

    // ---------- main loop ----------
    for (int c = 0; c < NCH; c++) {
        const uint32_t cur = (uint32_t)(c & 1) * STAGE;
        const uint32_t nxt = (uint32_t)((c + 1) & 1) * STAGE;

        if (c + 1 < NCH) {
            loadA(c + 1);
            cpB(c + 1, nxt);
        }

        // ---- compute chunk c: this warp handles k-steps {warp_k*2, warp_k*2+1}
        #pragma unroll
        for (int ksl = 0; ksl < 2; ksl++) {
            const uint32_t ks = (uint32_t)(warp_k * 2 + ksl);
            uint32_t ah[2][4], al[2][4];
            #pragma unroll
            for (int mt = 0; mt < 2; mt++) {
                uint32_t off = sw128((a_lrow + (uint32_t)mt * 16u) * 128u +
                                     ks * 32u + a_lsub);
                ldsm4(sb + cur + AH + off, ah[mt][0], ah[mt][1], ah[mt][2], ah[mt][3]);
                ldsm4(sb + cur + AL + off, al[mt][0], al[mt][1], al[mt][2], al[mt][3]);
            }
            #pragma unroll
            for (int h = 0; h < 2; h++) {        // two 4-nf halves: caps B frag regs
                uint32_t bh[4][2], bl[4][2];
                #pragma unroll
                for (int i = 0; i < 2; i++) {
                    uint32_t off = sw128((b_lrow0 + (uint32_t)(h * 2 + i) * 16u) * 128u +
                                         ks * 32u + b_lko);
                    ldsm4(sb + cur + BH + off, bh[2*i][0], bh[2*i][1],
                          bh[2*i+1][0], bh[2*i+1][1]);
                    ldsm4(sb + cur + BL + off, bl[2*i][0], bl[2*i][1],
                          bl[2*i+1][0], bl[2*i+1][1]);
                }
                #pragma unroll
                for (int mt = 0; mt < 2; mt++)
                    #pragma unroll
                    for (int j = 0; j < 4; j++) {
                        int nf = h * 4 + j;
                        mma16816(d[mt][nf], ah[mt], bh[j]);
                        mma16816(d[mt][nf], ah[mt], bl[j]);
                        mma16816(d[mt][nf], al[mt], bh[j]);
                    }
            }
        }

        if (c + 1 < NCH) storeA(nxt);
        asm volatile("cp.async.wait_all;" ::: "memory");
        __syncthreads();
    }

    // ---------- epilogue: two C buffers (k-split halves), bias in k0, sum on out
    float* C0 = reinterpret_cast<float*>(smc);            // 64 x 132 f32
    float* C1 = C0 + CELEMS;                              // 64 x 132 f32
    {
        float* C = warp_k ? C1 : C0;
        #pragma unroll
        for (int mt = 0; mt < 2; mt++) {
            int m0r = warp_m * 32 + mt * 16 + (lid >> 2);
            float b0v = warp_k ? 0.f : sbias[m0r];
            float b1v = warp_k ? 0.f : sbias[m0r + 8];
            #pragma unroll
            for (int nf = 0; nf < 8; nf++) {
                int nc = warp_n * 64 + nf * 8 + (lid & 3) * 2;
                float2 v0 = { d[mt][nf][0] + b0v, d[mt][nf][1] + b0v };
                float2 v1 = { d[mt][nf][2] + b1v, d[mt][nf][3] + b1v };
                *reinterpret_cast<float2*>(&C[(size_t)m0r * CSTRIDE + nc])       = v0;
                *reinterpret_cast<float2*>(&C[(size_t)(m0r + 8) * CSTRIDE + nc]) = v1;
            }
        }
    }
    __syncthreads();

    {
        // thread (n_loc, q): n_loc = output row within tile (0..127), q = 0/1
        // reads C[s][n_loc], s = q*4 + k*8 (+0..3): conflict-free
        const int n_loc = tid >> 1;
        const int q     = tid & 1;
        float* orow = out + (size_t)(n0 + n_loc) * S_ALL + s0;
        #pragma unroll
        for (int k = 0; k < 8; k++) {
            int s = q * 4 + k * 8;
            float4 v;
            v.x = C0[(size_t)(s + 0) * CSTRIDE + n_loc] + C1[(size_t)(s + 0) * CSTRIDE + n_loc];
            v.y = C0[(size_t)(s + 1) * CSTRIDE + n_loc] + C1[(size_t)(s + 1) * CSTRIDE + n_loc];
            v.z = C0[(size_t)(s + 2) * CSTRIDE + n_loc] + C1[(size_t)(s + 2) * CSTRIDE + n_loc];
            v.w = C0[(size_t)(s + 3) * CSTRIDE + n_loc] + C1[(size_t)(s + 3) * CSTRIDE + n_loc];
            *reinterpret_cast<float4*>(orow + s) = v;
        }
    }
}

extern "C" void kernel_launch(void* const* d_in, const int* in_sizes, int n_in,
                              void* d_out, int out_size)
{
    const float* x    = (const float*)d_in[0];
    const float* w    = (const float*)d_in[1];
    const float* bias = (const float*)d_in[2];
    const int*   ids  = (const int*)d_in[3];
    float*       out  = (float*)d_out;

    cudaFuncSetAttribute(lsh_mma_gemm, cudaFuncAttributeMaxDynamicSharedMemorySize,
                         SMEM_BYTES);

    split_x_kernel<<<128, 256>>>(x);
    dim3 grid(NX / NTILE, S_ALL / STILE);   // (2, 512): n-half fastest -> L2 reuse
    lsh_mma_gemm<<<grid, THREADS, SMEM_BYTES>>>(w, bias, ids, out);
}

// round 9
// speedup vs baseline: 1.0817x; 1.0433x over previous
#include <cuda_runtime.h>
#include <cuda_bf16.h>
#include <cstdint>

// out[n][s] = dot(x[n,:], weight[ids[s],:]) + bias[ids[s]]
//   x [256,512] f32, weight [500001,512] f32, bias [500001] f32, ids [32768] i32
//   out [256, 32768] f32
// Round 9: single-pass TF32 mma.sync (m16n8k8). R6 skeleton: KC=64, 8 chunks,
// CTA tile 64x128, 8 warps (2x4) of 32x32, 96KB double buffer, 2 CTAs/SM.
// MMA count / tensor cycles cut vs bf16x3; smem traffic unchanged.
// Expected rel_err ~3e-4 (tf32 u=2^-12, random cancellation over K=512).

namespace {
constexpr int D_K    = 512;
constexpr int NX     = 256;
constexpr int S_ALL  = 32768;
constexpr int ROWS_W = 500001;
constexpr int STILE  = 64;         // samples per CTA (GEMM M)
constexpr int NTILE  = 128;        // x rows per CTA (GEMM N)
constexpr int KC     = 64;         // f32 K elems per chunk
constexpr int NCH    = D_K / KC;   // 8
constexpr int THREADS = 256;

// stage layout (bytes): A 64 rows x 256B (f32), B 128 rows x 256B (f32)
constexpr uint32_t A_OFF = 0;          // 16KB
constexpr uint32_t B_OFF = 16384;      // 32KB
constexpr uint32_t STAGE = 49152;      // 48KB
constexpr uint32_t SMEM_BYTES = 2 * STAGE;   // 96KB (epilogue reuses this)
constexpr int CSTRIDE = 132;           // f32 stride of epilogue staging (64 x 132)
}

__device__ float g_xt[NX * D_K];       // x pre-rounded to tf32

__device__ __forceinline__ uint32_t smem_u32(const void* p) {
    uint32_t a;
    asm("{ .reg .u64 t; cvta.to.shared.u64 t, %1; cvt.u32.u64 %0, t; }" : "=r"(a) : "l"(p));
    return a;
}
// swizzle for 256B rows: XOR bits[6:4] with bits[10:8] (row & 7)
__device__ __forceinline__ uint32_t sw256(uint32_t o) { return o ^ ((o >> 4) & 0x70u); }

__device__ __forceinline__ uint32_t cvt_tf32(float v) {
    uint32_t r;
    asm("cvt.rna.tf32.f32 %0, %1;" : "=r"(r) : "f"(v));
    return r;
}
__device__ __forceinline__ void ldsm4(uint32_t addr, uint32_t& r0, uint32_t& r1,
                                      uint32_t& r2, uint32_t& r3) {
    asm volatile("ldmatrix.sync.aligned.m8n8.x4.shared.b16 {%0,%1,%2,%3}, [%4];"
                 : "=r"(r0), "=r"(r1), "=r"(r2), "=r"(r3) : "r"(addr));
}
__device__ __forceinline__ void mma_tf32(float* d, const uint32_t* a, const uint32_t* b) {
    asm volatile(
        "mma.sync.aligned.m16n8k8.row.col.f32.tf32.tf32.f32 "
        "{%0,%1,%2,%3}, {%4,%5,%6,%7}, {%8,%9}, {%0,%1,%2,%3};"
        : "+f"(d[0]), "+f"(d[1]), "+f"(d[2]), "+f"(d[3])
        : "r"(a[0]), "r"(a[1]), "r"(a[2]), "r"(a[3]), "r"(b[0]), "r"(b[1]));
}
__device__ __forceinline__ void cp16(uint32_t dst, const void* src) {
    asm volatile("cp.async.ca.shared.global [%0], [%1], 16;" :: "r"(dst), "l"(src));
}

// ---------- kernel 1: round x to tf32 ----------
__global__ void round_x_kernel(const float* __restrict__ x) {
    int i = blockIdx.x * blockDim.x + threadIdx.x;   // over 32768 float4s
    float4 v = reinterpret_cast<const float4*>(x)[i];
    uint4 t;
    t.x = cvt_tf32(v.x); t.y = cvt_tf32(v.y);
    t.z = cvt_tf32(v.z); t.w = cvt_tf32(v.w);
    reinterpret_cast<uint4*>(g_xt)[i] = t;
}

// ---------- kernel 2: GEMM ----------
__global__ void __launch_bounds__(THREADS, 2)
lsh_mma_gemm(const float* __restrict__ weight,
             const float* __restrict__ bias,
             const int* __restrict__ sample_ids,
             float* __restrict__ out)
{
    extern __shared__ float4 smem4[];
    char* smc = reinterpret_cast<char*>(smem4);
    const uint32_t sb = smem_u32(smc);

    __shared__ int   sids[STILE];
    __shared__ float sbias[STILE];

    const int tid = threadIdx.x;
    const int wid = tid >> 5;
    const int lid = tid & 31;
    const int n0  = blockIdx.x * NTILE;    // x-row half (0 or 128)
    const int s0  = blockIdx.y * STILE;    // sample tile

    if (tid < STILE) {
        int id = sample_ids[s0 + tid];
        id = min(max(id, 0), ROWS_W - 1);
        sids[tid]  = id;
        sbias[tid] = bias[id];
    }
    __syncthreads();

    // ---- loader coords: A = 64 gathered weight rows, 4 threads/row ----
    const int arow = tid >> 2;               // 0..63
    const int aq   = (tid & 3) * 16;         // 16-float segment within 64-float row

    // ---- warp / mma coords: 2(M) x 4(N), warp tile 32x32 ----
    const int warp_m = wid & 1;
    const int warp_n = wid >> 1;
    // ldmatrix lane row/col pieces (shared form for A and B x4 loads)
    const uint32_t l_row = (uint32_t)((lid & 7) + ((lid >> 3) & 1) * 8);
    const uint32_t l_k   = (uint32_t)(lid >> 4) * 4u;     // f32 col offset

    const uint32_t a_rb0 = ((uint32_t)(warp_m * 32) + l_row) * 256u;  // mt adds 16*256
    const uint32_t b_rb0 = ((uint32_t)(warp_n * 32) + l_row) * 256u;  // nf2 adds 16*256

    float d[2][4][4];
    #pragma unroll
    for (int mt = 0; mt < 2; mt++)
        #pragma unroll
        for (int nf = 0; nf < 4; nf++)
            #pragma unroll
            for (int r = 0; r < 4; r++) d[mt][nf][r] = 0.f;

    float4 av[4];

    auto loadA = [&](int c) {
        const float* wrow = weight + (size_t)sids[arow] * D_K + c * KC + aq;
        #pragma unroll
        for (int j = 0; j < 4; j++) av[j] = reinterpret_cast<const float4*>(wrow)[j];
    };
    auto cpB = [&](int c, uint32_t stg) {
        #pragma unroll
        for (int p = 0; p < 8; p++) {
            int idx = tid + p * THREADS;     // 2048 segs: 128 rows x 16 segs of 16B
            int row = idx >> 4, sg = idx & 15;
            const float* src = g_xt + (size_t)(n0 + row) * D_K + c * KC + sg * 4;
            uint32_t dst = sb + stg + B_OFF + sw256((uint32_t)row * 256u + (uint32_t)sg * 16u);
            cp16(dst, src);
        }
    };
    auto storeA = [&](uint32_t stg) {
        #pragma unroll
        for (int j = 0; j < 4; j++) {
            float4 v = av[j];
            uint4 t;
            t.x = cvt_tf32(v.x); t.y = cvt_tf32(v.y);
            t.z = cvt_tf32(v.z); t.w = cvt_tf32(v.w);
            uint32_t o = sw256((uint32_t)arow * 256u + (uint32_t)(aq + j * 4) * 4u);
            *reinterpret_cast<uint4*>(smc + stg + A_OFF + o) = t;
        }
    };

    // ---------- prologue: chunk 0 ----------
    loadA(0);
    cpB(0, 0);
    storeA(0);
    asm volatile("cp.async.wait_all;" ::: "memory");
    __syncthreads();

    // ---------- main loop ----------
    for (int c = 0; c < NCH; c++) {
        const uint32_t cur = (uint32_t)(c & 1) * STAGE;
        const uint32_t nxt = (uint32_t)((c + 1) & 1) * STAGE;

        if (c + 1 < NCH) {
            loadA(c + 1);
            cpB(c + 1, nxt);
        }

        // ---- compute chunk c: 8 k-steps of 8 ----
        #pragma unroll
        for (int ks8 = 0; ks8 < 8; ks8++) {
            const uint32_t kb = ((uint32_t)ks8 * 8u + l_k) * 4u;   // byte col
            uint32_t a[2][4], b[4][2];
            #pragma unroll
            for (int mt = 0; mt < 2; mt++) {
                uint32_t off = sw256(a_rb0 + (uint32_t)mt * 4096u + kb);
                ldsm4(sb + cur + A_OFF + off, a[mt][0], a[mt][1], a[mt][2], a[mt][3]);
            }
            #pragma unroll
            for (int nf2 = 0; nf2 < 2; nf2++) {
                uint32_t off = sw256(b_rb0 + (uint32_t)nf2 * 4096u + kb);
                // x4 over 16 n-rows: r0/r2 -> nf(2*nf2), r1/r3 -> nf(2*nf2+1)
                ldsm4(sb + cur + B_OFF + off, b[2*nf2][0], b[2*nf2+1][0],
                      b[2*nf2][1], b[2*nf2+1][1]);
            }
            #pragma unroll
            for (int mt = 0; mt < 2; mt++)
                #pragma unroll
                for (int nf = 0; nf < 4; nf++)
                    mma_tf32(d[mt][nf], a[mt], b[nf]);
        }

        if (c + 1 < NCH) storeA(nxt);
        asm volatile("cp.async.wait_all;" ::: "memory");
        __syncthreads();
    }

    // ---------- epilogue: smem transpose [m][n] stride 132, bias, coalesced out
    float* C = reinterpret_cast<float*>(smc);   // 64 x 132 f32 = 33.8KB
    #pragma unroll
    for (int mt = 0; mt < 2; mt++) {
        int m0r = warp_m * 32 + mt * 16 + (lid >> 2);
        float b0v = sbias[m0r];
        float b1v = sbias[m0r + 8];
        #pragma unroll
        for (int nf = 0; nf < 4; nf++) {
            int nc = warp_n * 32 + nf * 8 + (lid & 3) * 2;
            float2 v0 = { d[mt][nf][0] + b0v, d[mt][nf][1] + b0v };
            float2 v1 = { d[mt][nf][2] + b1v, d[mt][nf][3] + b1v };
            *reinterpret_cast<float2*>(&C[(size_t)m0r * CSTRIDE + nc])       = v0;
            *reinterpret_cast<float2*>(&C[(size_t)(m0r + 8) * CSTRIDE + nc]) = v1;
        }
    }
    __syncthreads();

    {
        // thread (n_loc, q): n_loc = output row within tile (0..127), q = 0/1
        const int n_loc = tid >> 1;
        const int q     = tid & 1;
        float* orow = out + (size_t)(n0 + n_loc) * S_ALL + s0;
        #pragma unroll
        for (int k = 0; k < 8; k++) {
            int s = q * 4 + k * 8;
            float4 v;
            v.x = C[(size_t)(s + 0) * CSTRIDE + n_loc];
            v.y = C[(size_t)(s + 1) * CSTRIDE + n_loc];
            v.z = C[(size_t)(s + 2) * CSTRIDE + n_loc];
            v.w = C[(size_t)(s + 3) * CSTRIDE + n_loc];
            *reinterpret_cast<float4*>(orow + s) = v;
        }
    }
}

extern "C" void kernel_launch(void* const* d_in, const int* in_sizes, int n_in,
                              void* d_out, int out_size)
{
    const float* x    = (const float*)d_in[0];
    const float* w    = (const float*)d_in[1];
    const float* bias = (const float*)d_in[2];
    const int*   ids  = (const int*)d_in[3];
    float*       out  = (float*)d_out;

    cudaFuncSetAttribute(lsh_mma_gemm, cudaFuncAttributeMaxDynamicSharedMemorySize,
                         SMEM_BYTES);

    round_x_kernel<<<128, 256>>>(x);
    dim3 grid(NX / NTILE, S_ALL / STILE);   // (2, 512): n-half fastest -> L2 reuse
    lsh_mma_gemm<<<grid, THREADS, SMEM_BYTES>>>(w, bias, ids, out);
}

// round 10
// speedup vs baseline: 1.4252x; 1.3175x over previous
#include <cuda_runtime.h>
#include <cuda_bf16.h>
#include <cstdint>

// out[n][s] = dot(x[n,:], weight[ids[s],:]) + bias[ids[s]]
//   x [256,512] f32, weight [500001,512] f32, bias [500001] f32, ids [32768] i32
//   out [256, 32768] f32
// Round 10: TF32 mma.sync, warp tile 64x64 (8 MAC per ldsm byte, 2x R9),
// CTA 128x128, 4 warps / 128 threads, KC=32, 64KB double buffer, 2 CTAs/SM.

namespace {
constexpr int D_K    = 512;
constexpr int NX     = 256;
constexpr int S_ALL  = 32768;
constexpr int ROWS_W = 500001;
constexpr int STILE  = 128;        // samples per CTA (GEMM M)
constexpr int NTILE  = 128;        // x rows per CTA (GEMM N)
constexpr int KC     = 32;         // f32 K elems per chunk
constexpr int NCH    = D_K / KC;   // 16
constexpr int THREADS = 128;

// stage layout (bytes): A 128 rows x 128B (f32), B 128 rows x 128B (f32)
constexpr uint32_t A_OFF = 0;          // 16KB
constexpr uint32_t B_OFF = 16384;      // 16KB
constexpr uint32_t STAGE = 32768;      // 32KB
// dynamic smem must fit 2 stages (64KB) AND epilogue C (128 x 132 f32 = 67.6KB)
constexpr uint32_t SMEM_BYTES = 69632; // 68KB
constexpr int CSTRIDE = 132;           // C is [n][m] with stride 132 f32
}

__device__ float g_xt[NX * D_K];       // x pre-rounded to tf32

__device__ __forceinline__ uint32_t smem_u32(const void* p) {
    uint32_t a;
    asm("{ .reg .u64 t; cvta.to.shared.u64 t, %1; cvt.u32.u64 %0, t; }" : "=r"(a) : "l"(p));
    return a;
}
__device__ __forceinline__ uint32_t sw128(uint32_t o) { return o ^ ((o >> 3) & 0x70u); }

__device__ __forceinline__ uint32_t cvt_tf32(float v) {
    uint32_t r;
    asm("cvt.rna.tf32.f32 %0, %1;" : "=r"(r) : "f"(v));
    return r;
}
__device__ __forceinline__ void ldsm4(uint32_t addr, uint32_t& r0, uint32_t& r1,
                                      uint32_t& r2, uint32_t& r3) {
    asm volatile("ldmatrix.sync.aligned.m8n8.x4.shared.b16 {%0,%1,%2,%3}, [%4];"
                 : "=r"(r0), "=r"(r1), "=r"(r2), "=r"(r3) : "r"(addr));
}
__device__ __forceinline__ void mma_tf32(float* d, const uint32_t* a, const uint32_t* b) {
    asm volatile(
        "mma.sync.aligned.m16n8k8.row.col.f32.tf32.tf32.f32 "
        "{%0,%1,%2,%3}, {%4,%5,%6,%7}, {%8,%9}, {%0,%1,%2,%3};"
        : "+f"(d[0]), "+f"(d[1]), "+f"(d[2]), "+f"(d[3])
        : "r"(a[0]), "r"(a[1]), "r"(a[2]), "r"(a[3]), "r"(b[0]), "r"(b[1]));
}
__device__ __forceinline__ void cp16(uint32_t dst, const void* src) {
    asm volatile("cp.async.ca.shared.global [%0], [%1], 16;" :: "r"(dst), "l"(src));
}

// ---------- kernel 1: round x to tf32 ----------
__global__ void round_x_kernel(const float* __restrict__ x) {
    int i = blockIdx.x * blockDim.x + threadIdx.x;   // over 32768 float4s
    float4 v = reinterpret_cast<const float4*>(x)[i];
    uint4 t;
    t.x = cvt_tf32(v.x); t.y = cvt_tf32(v.y);
    t.z = cvt_tf32(v.z); t.w = cvt_tf32(v.w);
    reinterpret_cast<uint4*>(g_xt)[i] = t;
}

// ---------- kernel 2: GEMM ----------
__global__ void __launch_bounds__(THREADS, 2)
lsh_mma_gemm(const float* __restrict__ weight,
             const float* __restrict__ bias,
             const int* __restrict__ sample_ids,
             float* __restrict__ out)
{
    extern __shared__ float4 smem4[];
    char* smc = reinterpret_cast<char*>(smem4);
    const uint32_t sb = smem_u32(smc);

    __shared__ int   sids[STILE];
    __shared__ float sbias[STILE];

    const int tid = threadIdx.x;
    const int wid = tid >> 5;
    const int lid = tid & 31;
    const int n0  = blockIdx.x * NTILE;    // x-row half (0 or 128)
    const int s0  = blockIdx.y * STILE;    // sample tile

    {
        int id = sample_ids[s0 + tid];
        id = min(max(id, 0), ROWS_W - 1);
        sids[tid]  = id;
        sbias[tid] = bias[id];
    }
    __syncthreads();

    // ---- loader coords: 128 rows x 8 segs of 16B; thread covers fixed seg ----
    const int l_sg   = tid & 7;              // 16B segment within 128B row
    const int l_rw0  = tid >> 3;             // base row (j adds 16)

    // ---- warp / mma coords: 2(M) x 2(N), warp tile 64x64 ----
    const int warp_m = wid & 1;
    const int warp_n = wid >> 1;
    const uint32_t l_row = (uint32_t)((lid & 7) + ((lid >> 3) & 1) * 8);
    const uint32_t l_k   = (uint32_t)(lid >> 4) * 4u;     // f32 col offset

    const uint32_t a_rb0 = ((uint32_t)(warp_m * 64) + l_row) * 128u;  // mt adds 16*128
    const uint32_t b_rb0 = ((uint32_t)(warp_n * 64) + l_row) * 128u;  // nf2 adds 16*128

    float d[4][8][4];
    #pragma unroll
    for (int mt = 0; mt < 4; mt++)
        #pragma unroll
        for (int nf = 0; nf < 8; nf++)
            #pragma unroll
            for (int r = 0; r < 4; r++) d[mt][nf][r] = 0.f;

    float4 av[8];

    auto loadA = [&](int c) {
        #pragma unroll
        for (int j = 0; j < 8; j++) {
            int row = l_rw0 + j * 16;
            av[j] = *reinterpret_cast<const float4*>(
                weight + (size_t)sids[row] * D_K + c * KC + l_sg * 4);
        }
    };
    auto storeA = [&](uint32_t stg) {
        #pragma unroll
        for (int j = 0; j < 8; j++) {
            int row = l_rw0 + j * 16;
            uint4 t;
            t.x = cvt_tf32(av[j].x); t.y = cvt_tf32(av[j].y);
            t.z = cvt_tf32(av[j].z); t.w = cvt_tf32(av[j].w);
            uint32_t o = sw128((uint32_t)row * 128u + (uint32_t)l_sg * 16u);
            *reinterpret_cast<uint4*>(smc + stg + A_OFF + o) = t;
        }
    };
    auto cpB = [&](int c, uint32_t stg) {
        #pragma unroll
        for (int j = 0; j < 8; j++) {
            int row = l_rw0 + j * 16;
            const float* src = g_xt + (size_t)(n0 + row) * D_K + c * KC + l_sg * 4;
            uint32_t dst = sb + stg + B_OFF +
                           sw128((uint32_t)row * 128u + (uint32_t)l_sg * 16u);
            cp16(dst, src);
        }
    };

    // ---------- prologue: chunk 0 ----------
    loadA(0);
    cpB(0, 0);
    storeA(0);
    asm volatile("cp.async.wait_all;" ::: "memory");
    __syncthreads();

    // ---------- main loop ----------
    for (int c = 0; c < NCH; c++) {
        const uint32_t cur = (uint32_t)(c & 1) * STAGE;
        const uint32_t nxt = (uint32_t)((c + 1) & 1) * STAGE;

        if (c + 1 < NCH) {
            loadA(c + 1);
            cpB(c + 1, nxt);
        }

        // ---- compute chunk c: 4 k-steps of 8 ----
        #pragma unroll
        for (int ks8 = 0; ks8 < 4; ks8++) {
            const uint32_t kb = ((uint32_t)ks8 * 8u + l_k) * 4u;   // byte col (<128)
            uint32_t a[4][4];
            #pragma unroll
            for (int mt = 0; mt < 4; mt++) {
                uint32_t off = sw128(a_rb0 + (uint32_t)mt * 2048u + kb);
                ldsm4(sb + cur + A_OFF + off, a[mt][0], a[mt][1], a[mt][2], a[mt][3]);
            }
            #pragma unroll
            for (int h = 0; h < 2; h++) {          // two nf-halves: caps B frag regs
                uint32_t b[4][2];
                #pragma unroll
                for (int i = 0; i < 2; i++) {
                    int nf2 = h * 2 + i;
                    uint32_t off = sw128(b_rb0 + (uint32_t)nf2 * 2048u + kb);
                    // x4 over 16 n-rows: r0/r2 -> nf even, r1/r3 -> nf odd
                    ldsm4(sb + cur + B_OFF + off, b[2*i][0], b[2*i+1][0],
                          b[2*i][1], b[2*i+1][1]);
                }
                #pragma unroll
                for (int mt = 0; mt < 4; mt++)
                    #pragma unroll
                    for (int j = 0; j < 4; j++)
                        mma_tf32(d[mt][h * 4 + j], a[mt], b[j]);
            }
        }

        if (c + 1 < NCH) storeA(nxt);
        asm volatile("cp.async.wait_all;" ::: "memory");
        __syncthreads();
    }

    // ---------- epilogue: C[n][m] stride 132 (conflict-free both phases) ----
    float* C = reinterpret_cast<float*>(smc);   // 128 x 132 f32 = 67.6KB
    #pragma unroll
    for (int mt = 0; mt < 4; mt++) {
        int m = warp_m * 64 + mt * 16 + (lid >> 2);
        float b0v = sbias[m];
        float b1v = sbias[m + 8];
        #pragma unroll
        for (int nf = 0; nf < 8; nf++) {
            int n = warp_n * 64 + nf * 8 + (lid & 3) * 2;
            C[(size_t)n * CSTRIDE + m]            = d[mt][nf][0] + b0v;
            C[(size_t)(n + 1) * CSTRIDE + m]      = d[mt][nf][1] + b0v;
            C[(size_t)n * CSTRIDE + m + 8]        = d[mt][nf][2] + b1v;
            C[(size_t)(n + 1) * CSTRIDE + m + 8]  = d[mt][nf][3] + b1v;
        }
    }
    __syncthreads();

    // read phase: warp w owns rows n = w*32..w*32+31; lanes span samples
    {
        #pragma unroll
        for (int j = 0; j < 32; j++) {
            int n = wid * 32 + j;
            float4 v = *reinterpret_cast<const float4*>(&C[(size_t)n * CSTRIDE + lid * 4]);
            *reinterpret_cast<float4*>(out + (size_t)(n0 + n) * S_ALL + s0 + lid * 4) = v;
        }
    }
}

extern "C" void kernel_launch(void* const* d_in, const int* in_sizes, int n_in,
                              void* d_out, int out_size)
{
    const float* x    = (const float*)d_in[0];
    const float* w    = (const float*)d_in[1];
    const float* bias = (const float*)d_in[2];
    const int*   ids  = (const int*)d_in[3];
    float*       out  = (float*)d_out;

    cudaFuncSetAttribute(lsh_mma_gemm, cudaFuncAttributeMaxDynamicSharedMemorySize,
                         SMEM_BYTES);

    round_x_kernel<<<128, 256>>>(x);
    dim3 grid(NX / NTILE, S_ALL / STILE);   // (2, 256): n-half fastest -> L2 reuse
    lsh_mma_gemm<<<grid, THREADS, SMEM_BYTES>>>(w, bias, ids, out);
}